// round 2
// baseline (speedup 1.0000x reference)
#include <cuda_runtime.h>
#include <cuda_bf16.h>
#include <math.h>

// Problem constants: B=2, L=4096, H=8, D=64, FACTOR=5 -> U_part = u = 45
#define L_SEQ 4096
#define NH 8
#define NB 2
#define DDIM 64
#define NU 45
#define NS 45
#define NBH 16
#define NIDX (L_SEQ * NS)      // 184320
#define CHUNK 128
#define NCHUNK 32              // 4096 / 128
#define PART_STRIDE 66         // m, l, acc[64]
#define NEG_BIG (-1e30f)

// ---------------- scratch (no allocations allowed) ----------------
__device__ int   g_idx[NIDX];                            // sample indices
__device__ float g_M[NBH * L_SEQ];                       // sparsity metric
__device__ int   g_topk[NBH * NU];                       // selected queries
__device__ float g_part[NBH * NCHUNK * NU * PART_STRIDE];// split-K partials

// ---------------- threefry2x32 (JAX-compatible) ----------------
#define TF_ROUND(x0, x1, r) do { (x0) += (x1); (x1) = ((x1) << (r)) | ((x1) >> (32 - (r))); (x1) ^= (x0); } while (0)

__host__ __device__ inline void tf2x32(unsigned k0, unsigned k1, unsigned &x0, unsigned &x1) {
    unsigned ks0 = k0, ks1 = k1, ks2 = k0 ^ k1 ^ 0x1BD11BDAu;
    x0 += ks0; x1 += ks1;
    TF_ROUND(x0, x1, 13); TF_ROUND(x0, x1, 15); TF_ROUND(x0, x1, 26); TF_ROUND(x0, x1, 6);
    x0 += ks1; x1 += ks2 + 1u;
    TF_ROUND(x0, x1, 17); TF_ROUND(x0, x1, 29); TF_ROUND(x0, x1, 16); TF_ROUND(x0, x1, 24);
    x0 += ks2; x1 += ks0 + 2u;
    TF_ROUND(x0, x1, 13); TF_ROUND(x0, x1, 15); TF_ROUND(x0, x1, 26); TF_ROUND(x0, x1, 6);
    x0 += ks0; x1 += ks1 + 3u;
    TF_ROUND(x0, x1, 17); TF_ROUND(x0, x1, 29); TF_ROUND(x0, x1, 16); TF_ROUND(x0, x1, 24);
    x0 += ks1; x1 += ks2 + 4u;
    TF_ROUND(x0, x1, 13); TF_ROUND(x0, x1, 15); TF_ROUND(x0, x1, 26); TF_ROUND(x0, x1, 6);
    x0 += ks2; x1 += ks0 + 5u;
}

// Partitionable threefry (modern JAX default):
// random_bits(key, 32, shape): element i uses counter (hi,lo) = (0, i);
// 32-bit output = out0 ^ out1.  randint with span 4096 (power of two)
// reduces to lower_bits & 0xFFF, lower_bits from the SECOND child of
// split(key(1)) (foldlike split: child j = both lanes of tf(key,(0,j))).
__global__ void k_idx(unsigned k2a, unsigned k2b) {
    int i = blockIdx.x * blockDim.x + threadIdx.x;
    if (i >= NIDX) return;
    unsigned x0 = 0u, x1 = (unsigned)i;
    tf2x32(k2a, k2b, x0, x1);
    g_idx[i] = (int)((x0 ^ x1) & 0xFFFu);
}

// ---------------- M metric: warp per (b,h,q) ----------------
__global__ void k_M(const float* __restrict__ Q, const float* __restrict__ K) {
    int warp = (blockIdx.x * blockDim.x + threadIdx.x) >> 5;
    int lane = threadIdx.x & 31;
    if (warp >= NBH * L_SEQ) return;
    int q = warp & (L_SEQ - 1);
    int bh = warp >> 12;
    int b = bh >> 3, h = bh & 7;

    const float2* Qrow = (const float2*)(Q + ((size_t)(b * L_SEQ + q) * NH + h) * DDIM);
    float2 qv = Qrow[lane];
    const float* Kbase = K + (size_t)b * (L_SEQ * NH * DDIM) + (size_t)h * DDIM;

    float mx = NEG_BIG, sm = 0.0f;
    const int* idxp = g_idx + q * NS;
#pragma unroll
    for (int s = 0; s < NS; s++) {
        int k = idxp[s];
        float2 kv = ((const float2*)(Kbase + (size_t)k * (NH * DDIM)))[lane];
        float p = qv.x * kv.x + qv.y * kv.y;
        p += __shfl_xor_sync(0xFFFFFFFFu, p, 16);
        p += __shfl_xor_sync(0xFFFFFFFFu, p, 8);
        p += __shfl_xor_sync(0xFFFFFFFFu, p, 4);
        p += __shfl_xor_sync(0xFFFFFFFFu, p, 2);
        p += __shfl_xor_sync(0xFFFFFFFFu, p, 1);
        mx = fmaxf(mx, p);
        sm += p;
    }
    if (lane == 0) g_M[warp] = mx - sm * (1.0f / (float)L_SEQ);
}

// ---------------- exact top-45 per (b,h): iterative argmax ----------------
// Packed key: ordered-float in high 32 bits, (4095 - q) in low 32 bits
// -> max picks highest value, ties broken by smallest q (matches lax.top_k).
__global__ void k_topk() {
    __shared__ unsigned long long sk[L_SEQ];
    __shared__ unsigned long long red[256];
    int bh = blockIdx.x;
    int t = threadIdx.x;
    for (int i = t; i < L_SEQ; i += 256) {
        unsigned u = __float_as_uint(g_M[bh * L_SEQ + i]);
        u = (u & 0x80000000u) ? ~u : (u | 0x80000000u);
        sk[i] = ((unsigned long long)u << 32) | (unsigned)(L_SEQ - 1 - i);
    }
    __syncthreads();
    for (int it = 0; it < NU; it++) {
        unsigned long long best = 0ull;
        for (int i = t; i < L_SEQ; i += 256) best = max(best, sk[i]);
        red[t] = best;
        __syncthreads();
        for (int off = 128; off; off >>= 1) {
            if (t < off) red[t] = max(red[t], red[t + off]);
            __syncthreads();
        }
        unsigned long long win = red[0];
        int q = (L_SEQ - 1) - (int)(win & 0xFFFFFFFFu);
        if (t == 0) {
            g_topk[bh * NU + it] = q;
            sk[q] = 0ull;
        }
        __syncthreads();
    }
}

// ---------------- attention partials: block per (bh, key-chunk) ----------------
__global__ void k_attn(const float* __restrict__ Q, const float* __restrict__ K,
                       const float* __restrict__ V, const int* __restrict__ mask) {
    __shared__ float sQ[NU * DDIM];     // 11.25 KB
    __shared__ float sS[NU * CHUNK];    // 22.5 KB
    int bh = blockIdx.x / NCHUNK, c = blockIdx.x % NCHUNK;
    int b = bh >> 3, h = bh & 7;
    int t = threadIdx.x, lane = t & 31, w = t >> 5;

    for (int i = t; i < NU * DDIM; i += 256) {
        int u = i >> 6, d = i & 63;
        int q = g_topk[bh * NU + u];
        sQ[i] = Q[((size_t)(b * L_SEQ + q) * NH + h) * DDIM + d];
    }
    __syncthreads();

    const float* Kbase = K + (size_t)b * (L_SEQ * NH * DDIM) + (size_t)h * DDIM;
    const float* Vbase = V + (size_t)b * (L_SEQ * NH * DDIM) + (size_t)h * DDIM;
    int k0 = c * CHUNK;

    // scores: warp per key, lanes split D
    for (int kk = w; kk < CHUNK; kk += 8) {
        int kg = k0 + kk;
        float2 kv = ((const float2*)(Kbase + (size_t)kg * (NH * DDIM)))[lane];
        int mk = mask[b * L_SEQ + kg];
#pragma unroll
        for (int u = 0; u < NU; u++) {
            float2 qv = ((const float2*)(sQ + u * DDIM))[lane];
            float p = qv.x * kv.x + qv.y * kv.y;
            p += __shfl_xor_sync(0xFFFFFFFFu, p, 16);
            p += __shfl_xor_sync(0xFFFFFFFFu, p, 8);
            p += __shfl_xor_sync(0xFFFFFFFFu, p, 4);
            p += __shfl_xor_sync(0xFFFFFFFFu, p, 2);
            p += __shfl_xor_sync(0xFFFFFFFFu, p, 1);
            if (lane == 0) sS[u * CHUNK + kk] = mk ? p * 0.125f : NEG_BIG;
        }
    }
    __syncthreads();

    // per-query: local softmax over chunk + V accumulation (warp per query)
    for (int u = w; u < NU; u += 8) {
        float m = NEG_BIG;
#pragma unroll
        for (int kk = lane; kk < CHUNK; kk += 32) m = fmaxf(m, sS[u * CHUNK + kk]);
#pragma unroll
        for (int o = 16; o; o >>= 1) m = fmaxf(m, __shfl_xor_sync(0xFFFFFFFFu, m, o));
        float l = 0.0f;
#pragma unroll
        for (int kk = lane; kk < CHUNK; kk += 32) {
            float s = sS[u * CHUNK + kk];
            float e = (s <= NEG_BIG) ? 0.0f : __expf(s - m);
            sS[u * CHUNK + kk] = e;
            l += e;
        }
#pragma unroll
        for (int o = 16; o; o >>= 1) l += __shfl_xor_sync(0xFFFFFFFFu, l, o);

        float2 acc = make_float2(0.0f, 0.0f);
#pragma unroll 4
        for (int kk = 0; kk < CHUNK; kk++) {
            float p = sS[u * CHUNK + kk];
            float2 vv = ((const float2*)(Vbase + (size_t)(k0 + kk) * (NH * DDIM)))[lane];
            acc.x += p * vv.x;
            acc.y += p * vv.y;
        }
        float* part = g_part + ((size_t)blockIdx.x * NU + u) * PART_STRIDE;
        if (lane == 0) { part[0] = m; part[1] = l; }
        part[2 + 2 * lane] = acc.x;
        part[3 + 2 * lane] = acc.y;
    }
}

// ---------------- combine split-K partials ----------------
__global__ void k_comb(float* __restrict__ out) {
    int bu = blockIdx.x;
    int bh = bu / NU, u = bu % NU;
    int b = bh >> 3, h = bh & 7;
    int d = threadIdx.x;

    float m = NEG_BIG;
#pragma unroll
    for (int c = 0; c < NCHUNK; c++)
        m = fmaxf(m, g_part[((size_t)(bh * NCHUNK + c) * NU + u) * PART_STRIDE]);
    float l = 0.0f, acc = 0.0f;
#pragma unroll
    for (int c = 0; c < NCHUNK; c++) {
        const float* part = g_part + ((size_t)(bh * NCHUNK + c) * NU + u) * PART_STRIDE;
        float mc = part[0];
        float sc = (mc <= NEG_BIG) ? 0.0f : __expf(mc - m);
        l += part[1] * sc;
        acc += sc * part[2 + d];
    }
    out[((size_t)(b * NU + u) * NH + h) * DDIM + d] = acc / l;
}

// ---------------- launch ----------------
extern "C" void kernel_launch(void* const* d_in, const int* in_sizes, int n_in,
                              void* d_out, int out_size) {
    const float* Q = (const float*)d_in[0];
    const float* K = (const float*)d_in[1];
    const float* V = (const float*)d_in[2];
    const int* mask = (const int*)d_in[3];
    float* out = (float*)d_out;

    // lower_key = second child of foldlike split(key(1)):
    // child 1 = both lanes of threefry2x32(key=(0,1), counter=(0,1)).
    unsigned s0 = 0u, s1 = 1u;
    tf2x32(0u, 1u, s0, s1);
    unsigned k2a = s0, k2b = s1;

    k_idx<<<(NIDX + 255) / 256, 256>>>(k2a, k2b);
    k_M<<<(NBH * L_SEQ) / 8, 256>>>(Q, K);
    k_topk<<<NBH, 256>>>();
    k_attn<<<NBH * NCHUNK, 256>>>(Q, K, V, mask);
    k_comb<<<NBH * NU, 64>>>(out);
}

// round 6
// speedup vs baseline: 1.9759x; 1.9759x over previous
#include <cuda_runtime.h>
#include <cuda_bf16.h>
#include <math.h>

// Problem constants: B=2, L=4096, H=8, D=64, FACTOR=5 -> U_part = u = 45
#define L_SEQ 4096
#define NH 8
#define DDIM 64
#define NU 45
#define NS 45
#define NBH 16
#define NIDX (L_SEQ * NS)      // 184320
#define CHUNK 64
#define NCHUNK 64              // 4096 / 64
#define PART_STRIDE 68         // [0]=m, [1]=l, [4..67]=acc (16B-aligned records)
#define NEG_BIG (-1e30f)
#define SKS_STRIDE 68          // multiple of 4 -> float4-aligned rows

// ---------------- scratch (no allocations allowed) ----------------
__device__ int   g_idx[NIDX];
__device__ float g_M[NBH * L_SEQ];
__device__ int   g_topk[NBH * NU];
__device__ float g_part[NBH * NCHUNK * NU * PART_STRIDE]; // 12.5 MB

// ---------------- threefry2x32 (JAX partitionable) ----------------
#define TF_ROUND(x0, x1, r) do { (x0) += (x1); (x1) = ((x1) << (r)) | ((x1) >> (32 - (r))); (x1) ^= (x0); } while (0)

__host__ __device__ inline void tf2x32(unsigned k0, unsigned k1, unsigned &x0, unsigned &x1) {
    unsigned ks0 = k0, ks1 = k1, ks2 = k0 ^ k1 ^ 0x1BD11BDAu;
    x0 += ks0; x1 += ks1;
    TF_ROUND(x0, x1, 13); TF_ROUND(x0, x1, 15); TF_ROUND(x0, x1, 26); TF_ROUND(x0, x1, 6);
    x0 += ks1; x1 += ks2 + 1u;
    TF_ROUND(x0, x1, 17); TF_ROUND(x0, x1, 29); TF_ROUND(x0, x1, 16); TF_ROUND(x0, x1, 24);
    x0 += ks2; x1 += ks0 + 2u;
    TF_ROUND(x0, x1, 13); TF_ROUND(x0, x1, 15); TF_ROUND(x0, x1, 26); TF_ROUND(x0, x1, 6);
    x0 += ks0; x1 += ks1 + 3u;
    TF_ROUND(x0, x1, 17); TF_ROUND(x0, x1, 29); TF_ROUND(x0, x1, 16); TF_ROUND(x0, x1, 24);
    x0 += ks1; x1 += ks2 + 4u;
    TF_ROUND(x0, x1, 13); TF_ROUND(x0, x1, 15); TF_ROUND(x0, x1, 26); TF_ROUND(x0, x1, 6);
    x0 += ks2; x1 += ks0 + 5u;
}

// random_bits: element i uses counter (0, i); 32-bit output = out0 ^ out1.
// randint span 4096 -> & 0xFFF. Key = 2nd foldlike-split child of key(1).
__global__ void k_idx(unsigned k2a, unsigned k2b) {
    int i = blockIdx.x * blockDim.x + threadIdx.x;
    if (i >= NIDX) return;
    unsigned x0 = 0u, x1 = (unsigned)i;
    tf2x32(k2a, k2b, x0, x1);
    g_idx[i] = (int)((x0 ^ x1) & 0xFFFu);
}

// ---------------- M metric: warp per (b,h,q), half-warp per sample ----------------
__global__ void k_M(const float* __restrict__ Q, const float* __restrict__ K) {
    int warp = (blockIdx.x * blockDim.x + threadIdx.x) >> 5;
    int lane = threadIdx.x & 31;
    if (warp >= NBH * L_SEQ) return;
    int q = warp & (L_SEQ - 1);
    int bh = warp >> 12;
    int b = bh >> 3, h = bh & 7;
    int hw = lane >> 4, ld = lane & 15;      // half-warp id, d-group (float4)

    float4 qv = *(const float4*)(Q + ((size_t)(b * L_SEQ + q) * NH + h) * DDIM + 4 * ld);
    const float* Kb = K + (size_t)b * (L_SEQ * NH * DDIM) + (size_t)h * DDIM;
    const int* idxp = g_idx + q * NS;

    float mx = NEG_BIG, sm = 0.0f;
#pragma unroll
    for (int s = 0; s < NS; s += 2) {
        int s0 = s + hw;
        int i = (s0 < NS) ? s0 : (NS - 1);   // clamp tail
        int k = idxp[i];
        float4 kv = *(const float4*)(Kb + (size_t)k * (NH * DDIM) + 4 * ld);
        float p = qv.x * kv.x + qv.y * kv.y + qv.z * kv.z + qv.w * kv.w;
        p += __shfl_xor_sync(0xFFFFFFFFu, p, 8);
        p += __shfl_xor_sync(0xFFFFFFFFu, p, 4);
        p += __shfl_xor_sync(0xFFFFFFFFu, p, 2);
        p += __shfl_xor_sync(0xFFFFFFFFu, p, 1);
        if (s0 < NS) { mx = fmaxf(mx, p); sm += p; }
    }
    mx = fmaxf(mx, __shfl_xor_sync(0xFFFFFFFFu, mx, 16));
    sm += __shfl_xor_sync(0xFFFFFFFFu, sm, 16);
    if (lane == 0) g_M[warp] = mx - sm * (1.0f / (float)L_SEQ);
}

// ---------------- exact top-45 per (b,h): iterative argmax (shfl reduce) ----------------
__global__ void k_topk() {
    __shared__ unsigned long long sk[L_SEQ];
    __shared__ unsigned long long red[8];
    int bh = blockIdx.x;
    int t = threadIdx.x, lane = t & 31, w = t >> 5;
    for (int i = t; i < L_SEQ; i += 256) {
        unsigned u = __float_as_uint(g_M[bh * L_SEQ + i]);
        u = (u & 0x80000000u) ? ~u : (u | 0x80000000u);
        sk[i] = ((unsigned long long)u << 32) | (unsigned)(L_SEQ - 1 - i);
    }
    __syncthreads();
    for (int it = 0; it < NU; it++) {
        unsigned long long best = 0ull;
#pragma unroll
        for (int i = t; i < L_SEQ; i += 256) best = max(best, sk[i]);
#pragma unroll
        for (int off = 16; off; off >>= 1) {
            unsigned long long o = __shfl_xor_sync(0xFFFFFFFFu, best, off);
            best = max(best, o);
        }
        if (lane == 0) red[w] = best;
        __syncthreads();
        if (t < 8) {
            unsigned long long b2 = red[t];
#pragma unroll
            for (int off = 4; off; off >>= 1) {
                unsigned long long o = __shfl_xor_sync(0xFFu, b2, off);
                b2 = max(b2, o);
            }
            if (t == 0) {
                int q = (L_SEQ - 1) - (int)(b2 & 0xFFFFFFFFu);
                g_topk[bh * NU + it] = q;
                sk[q] = 0ull;
            }
        }
        __syncthreads();
    }
}

// ---------------- attention partials: register-tiled GEMMs ----------------
// Block: (bh, 64-key chunk), 256 threads. tk = t&15 (k/d group of 4), tu = t>>4 (u group of 3).
__global__ void __launch_bounds__(256) k_attn(const float* __restrict__ Q, const float* __restrict__ K,
                       const float* __restrict__ V, const int* __restrict__ mask) {
    __shared__ float sQt[64 * 49];              // [d][u], stride 49 (12.25 KB)
    __shared__ float sKS[64 * SKS_STRIDE];      // A: K^T [d][k]; reused as P [u][k] (17 KB)
    __shared__ float sV[64 * 64];               // [k][d] (16 KB)

    int bh = blockIdx.x >> 6, c = blockIdx.x & 63;
    int b = bh >> 3, h = bh & 7;
    int t = threadIdx.x;
    int tk = t & 15, tu = t >> 4;
    int k0 = c * CHUNK;

    // ---- load tiles ----
    for (int i = t; i < NU * 64; i += 256) {
        int u = i >> 6, d = i & 63;
        int q = g_topk[bh * NU + u];
        sQt[d * 49 + u] = Q[((size_t)(b * L_SEQ + q) * NH + h) * DDIM + d];
    }
    if (t < 192) {                              // zero-pad u = 45..47
        int u = 45 + (t >> 6), d = t & 63;
        sQt[d * 49 + u] = 0.0f;
    }
    for (int i = t; i < 64 * 64; i += 256) {
        int k = i >> 6, d = i & 63;
        sKS[d * SKS_STRIDE + k] = K[((size_t)(b * L_SEQ + k0 + k) * NH + h) * DDIM + d];
    }
    for (int i = t; i < 64 * 64; i += 256) {
        int k = i >> 6, d = i & 63;
        sV[(k << 6) + d] = V[((size_t)(b * L_SEQ + k0 + k) * NH + h) * DDIM + d];
    }
    __syncthreads();

    // ---- phase A: scores S = Q_sel @ K^T ----
    float acc[3][4];
#pragma unroll
    for (int i = 0; i < 3; i++)
#pragma unroll
        for (int j = 0; j < 4; j++) acc[i][j] = 0.0f;

#pragma unroll 4
    for (int d = 0; d < 64; d++) {
        float q0 = sQt[d * 49 + 3 * tu];
        float q1 = sQt[d * 49 + 3 * tu + 1];
        float q2 = sQt[d * 49 + 3 * tu + 2];
        float4 kv = *(float4*)&sKS[d * SKS_STRIDE + 4 * tk];
        acc[0][0] += q0 * kv.x; acc[0][1] += q0 * kv.y; acc[0][2] += q0 * kv.z; acc[0][3] += q0 * kv.w;
        acc[1][0] += q1 * kv.x; acc[1][1] += q1 * kv.y; acc[1][2] += q1 * kv.z; acc[1][3] += q1 * kv.w;
        acc[2][0] += q2 * kv.x; acc[2][1] += q2 * kv.y; acc[2][2] += q2 * kv.z; acc[2][3] += q2 * kv.w;
    }

    // mask + scale
    int mk[4];
#pragma unroll
    for (int j = 0; j < 4; j++) mk[j] = mask[b * L_SEQ + k0 + 4 * tk + j];
#pragma unroll
    for (int i = 0; i < 3; i++)
#pragma unroll
        for (int j = 0; j < 4; j++)
            acc[i][j] = mk[j] ? acc[i][j] * 0.125f : NEG_BIG;

    // softmax stats per u over the 16-lane half-warp (lanes share tu)
    float m_i[3], l_i[3];
#pragma unroll
    for (int i = 0; i < 3; i++) {
        float m = fmaxf(fmaxf(acc[i][0], acc[i][1]), fmaxf(acc[i][2], acc[i][3]));
        m = fmaxf(m, __shfl_xor_sync(0xFFFFFFFFu, m, 8));
        m = fmaxf(m, __shfl_xor_sync(0xFFFFFFFFu, m, 4));
        m = fmaxf(m, __shfl_xor_sync(0xFFFFFFFFu, m, 2));
        m = fmaxf(m, __shfl_xor_sync(0xFFFFFFFFu, m, 1));
        float l = 0.0f;
#pragma unroll
        for (int j = 0; j < 4; j++) {
            float e = (acc[i][j] <= 0.5f * NEG_BIG) ? 0.0f : __expf(acc[i][j] - m);
            acc[i][j] = e;
            l += e;
        }
        l += __shfl_xor_sync(0xFFFFFFFFu, l, 8);
        l += __shfl_xor_sync(0xFFFFFFFFu, l, 4);
        l += __shfl_xor_sync(0xFFFFFFFFu, l, 2);
        l += __shfl_xor_sync(0xFFFFFFFFu, l, 1);
        m_i[i] = m; l_i[i] = l;
    }
    __syncthreads();   // all reads of sKS (K^T) done

    // write P into sKS ([u][k]) + write m,l
#pragma unroll
    for (int i = 0; i < 3; i++) {
        int u = 3 * tu + i;
        *(float4*)&sKS[u * SKS_STRIDE + 4 * tk] = make_float4(acc[i][0], acc[i][1], acc[i][2], acc[i][3]);
        if (tk == 0 && u < NU) {
            float* part = g_part + ((size_t)blockIdx.x * NU + u) * PART_STRIDE;
            part[0] = m_i[i];
            part[1] = l_i[i];
        }
    }
    __syncthreads();

    // ---- phase B: O_partial = P @ V, thread tile 3u x 4d ----
    float ob[3][4];
#pragma unroll
    for (int i = 0; i < 3; i++)
#pragma unroll
        for (int j = 0; j < 4; j++) ob[i][j] = 0.0f;

#pragma unroll 4
    for (int kk = 0; kk < 64; kk++) {
        float p0 = sKS[(3 * tu) * SKS_STRIDE + kk];
        float p1 = sKS[(3 * tu + 1) * SKS_STRIDE + kk];
        float p2 = sKS[(3 * tu + 2) * SKS_STRIDE + kk];
        float4 vv = *(float4*)&sV[(kk << 6) + 4 * tk];
        ob[0][0] += p0 * vv.x; ob[0][1] += p0 * vv.y; ob[0][2] += p0 * vv.z; ob[0][3] += p0 * vv.w;
        ob[1][0] += p1 * vv.x; ob[1][1] += p1 * vv.y; ob[1][2] += p1 * vv.z; ob[1][3] += p1 * vv.w;
        ob[2][0] += p2 * vv.x; ob[2][1] += p2 * vv.y; ob[2][2] += p2 * vv.z; ob[2][3] += p2 * vv.w;
    }
#pragma unroll
    for (int i = 0; i < 3; i++) {
        int u = 3 * tu + i;
        if (u < NU) {
            float* part = g_part + ((size_t)blockIdx.x * NU + u) * PART_STRIDE;
            *(float4*)&part[4 + 4 * tk] = make_float4(ob[i][0], ob[i][1], ob[i][2], ob[i][3]);
        }
    }
}

// ---------------- combine split-K partials ----------------
__global__ void k_comb(float* __restrict__ out) {
    int bu = blockIdx.x;
    int bh = bu / NU, u = bu % NU;
    int b = bh >> 3, h = bh & 7;
    int d = threadIdx.x;

    float m = NEG_BIG;
#pragma unroll 8
    for (int c = 0; c < NCHUNK; c++)
        m = fmaxf(m, g_part[((size_t)(bh * NCHUNK + c) * NU + u) * PART_STRIDE]);
    float l = 0.0f, acc = 0.0f;
#pragma unroll 8
    for (int c = 0; c < NCHUNK; c++) {
        const float* part = g_part + ((size_t)(bh * NCHUNK + c) * NU + u) * PART_STRIDE;
        float mc = part[0];
        float sc = (mc <= 0.5f * NEG_BIG) ? 0.0f : __expf(mc - m);
        l += part[1] * sc;
        acc += sc * part[4 + d];
    }
    out[((size_t)(b * NU + u) * NH + h) * DDIM + d] = acc / l;
}

// ---------------- launch ----------------
extern "C" void kernel_launch(void* const* d_in, const int* in_sizes, int n_in,
                              void* d_out, int out_size) {
    const float* Q = (const float*)d_in[0];
    const float* K = (const float*)d_in[1];
    const float* V = (const float*)d_in[2];
    const int* mask = (const int*)d_in[3];
    float* out = (float*)d_out;

    // lower_key = 2nd child of foldlike split(key(1)) = tf2x32(key=(0,1), ctr=(0,1))
    unsigned s0 = 0u, s1 = 1u;
    tf2x32(0u, 1u, s0, s1);

    k_idx<<<(NIDX + 255) / 256, 256>>>(s0, s1);
    k_M<<<(NBH * L_SEQ) / 8, 256>>>(Q, K);
    k_topk<<<NBH, 256>>>();
    k_attn<<<NBH * NCHUNK, 256>>>(Q, K, V, mask);
    k_comb<<<NBH * NU, 64>>>(out);
}

// round 9
// speedup vs baseline: 2.0998x; 1.0628x over previous
#include <cuda_runtime.h>
#include <cuda_bf16.h>
#include <math.h>

// Problem constants: B=2, L=4096, H=8, D=64, FACTOR=5 -> U_part = u = 45
#define L_SEQ 4096
#define NH 8
#define DDIM 64
#define NU 45
#define NS 45
#define NBH 16
#define NIDX (L_SEQ * NS)      // 184320
#define CHUNK 128
#define NCHUNK 32              // 4096 / 128
#define PART_STRIDE 68         // [0]=m, [1]=l, [4..67]=acc (16B-aligned records)
#define NEG_BIG (-1e30f)
#define SKT_STRIDE 132         // K^T/P row stride (mult of 4 -> float4 rows)

// smem layout for k_attn (dynamic): sQt 64x48 | sKT 64x132 | sV 128x64
#define SQT_FLOATS (64 * 48)
#define SKT_FLOATS (64 * SKT_STRIDE)
#define SV_FLOATS  (128 * 64)
#define SMEM_BYTES ((SQT_FLOATS + SKT_FLOATS + SV_FLOATS) * 4)   // 78,848 B

// ---------------- scratch (no allocations allowed) ----------------
__device__ int   g_idx[NIDX];
__device__ float g_M[NBH * L_SEQ];
__device__ int   g_topk[NBH * NU];
__device__ float g_part[NBH * NCHUNK * NU * PART_STRIDE]; // 6.3 MB

// ---------------- threefry2x32 (JAX partitionable) ----------------
#define TF_ROUND(x0, x1, r) do { (x0) += (x1); (x1) = ((x1) << (r)) | ((x1) >> (32 - (r))); (x1) ^= (x0); } while (0)

__host__ __device__ inline void tf2x32(unsigned k0, unsigned k1, unsigned &x0, unsigned &x1) {
    unsigned ks0 = k0, ks1 = k1, ks2 = k0 ^ k1 ^ 0x1BD11BDAu;
    x0 += ks0; x1 += ks1;
    TF_ROUND(x0, x1, 13); TF_ROUND(x0, x1, 15); TF_ROUND(x0, x1, 26); TF_ROUND(x0, x1, 6);
    x0 += ks1; x1 += ks2 + 1u;
    TF_ROUND(x0, x1, 17); TF_ROUND(x0, x1, 29); TF_ROUND(x0, x1, 16); TF_ROUND(x0, x1, 24);
    x0 += ks2; x1 += ks0 + 2u;
    TF_ROUND(x0, x1, 13); TF_ROUND(x0, x1, 15); TF_ROUND(x0, x1, 26); TF_ROUND(x0, x1, 6);
    x0 += ks0; x1 += ks1 + 3u;
    TF_ROUND(x0, x1, 17); TF_ROUND(x0, x1, 29); TF_ROUND(x0, x1, 16); TF_ROUND(x0, x1, 24);
    x0 += ks1; x1 += ks2 + 4u;
    TF_ROUND(x0, x1, 13); TF_ROUND(x0, x1, 15); TF_ROUND(x0, x1, 26); TF_ROUND(x0, x1, 6);
    x0 += ks2; x1 += ks0 + 5u;
}

// random_bits: element i uses counter (0, i); output = out0 ^ out1; & 0xFFF.
__global__ void k_idx(unsigned k2a, unsigned k2b) {
    int i = blockIdx.x * blockDim.x + threadIdx.x;
    if (i >= NIDX) return;
    unsigned x0 = 0u, x1 = (unsigned)i;
    tf2x32(k2a, k2b, x0, x1);
    g_idx[i] = (int)((x0 ^ x1) & 0xFFFu);
}

// ---------------- M metric: warp per (b,h,q), half-warp per sample ----------------
__global__ void k_M(const float* __restrict__ Q, const float* __restrict__ K) {
    int warp = (blockIdx.x * blockDim.x + threadIdx.x) >> 5;
    int lane = threadIdx.x & 31;
    if (warp >= NBH * L_SEQ) return;
    int q = warp & (L_SEQ - 1);
    int bh = warp >> 12;
    int b = bh >> 3, h = bh & 7;
    int hw = lane >> 4, ld = lane & 15;

    float4 qv = *(const float4*)(Q + ((size_t)(b * L_SEQ + q) * NH + h) * DDIM + 4 * ld);
    const float* Kb = K + (size_t)b * (L_SEQ * NH * DDIM) + (size_t)h * DDIM;
    const int* idxp = g_idx + q * NS;

    float mx = NEG_BIG, sm = 0.0f;
#pragma unroll
    for (int s = 0; s < NS; s += 2) {
        int s0 = s + hw;
        int i = (s0 < NS) ? s0 : (NS - 1);
        int k = idxp[i];
        float4 kv = *(const float4*)(Kb + (size_t)k * (NH * DDIM) + 4 * ld);
        float p = qv.x * kv.x + qv.y * kv.y + qv.z * kv.z + qv.w * kv.w;
        p += __shfl_xor_sync(0xFFFFFFFFu, p, 8);
        p += __shfl_xor_sync(0xFFFFFFFFu, p, 4);
        p += __shfl_xor_sync(0xFFFFFFFFu, p, 2);
        p += __shfl_xor_sync(0xFFFFFFFFu, p, 1);
        if (s0 < NS) { mx = fmaxf(mx, p); sm += p; }
    }
    mx = fmaxf(mx, __shfl_xor_sync(0xFFFFFFFFu, mx, 16));
    sm += __shfl_xor_sync(0xFFFFFFFFu, sm, 16);
    if (lane == 0) g_M[warp] = mx - sm * (1.0f / (float)L_SEQ);
}

// ---------------- exact top-45 per (b,h): iterative argmax, 1024 threads ----------------
__global__ void __launch_bounds__(1024) k_topk() {
    __shared__ unsigned long long sk[L_SEQ];
    __shared__ unsigned long long red[32];
    int bh = blockIdx.x;
    int t = threadIdx.x, lane = t & 31, w = t >> 5;
    for (int i = t; i < L_SEQ; i += 1024) {
        unsigned u = __float_as_uint(g_M[bh * L_SEQ + i]);
        u = (u & 0x80000000u) ? ~u : (u | 0x80000000u);
        sk[i] = ((unsigned long long)u << 32) | (unsigned)(L_SEQ - 1 - i);
    }
    __syncthreads();
    for (int it = 0; it < NU; it++) {
        unsigned long long best = 0ull;
#pragma unroll
        for (int i = t; i < L_SEQ; i += 1024) best = max(best, sk[i]);
#pragma unroll
        for (int off = 16; off; off >>= 1) {
            unsigned long long o = __shfl_xor_sync(0xFFFFFFFFu, best, off);
            best = max(best, o);
        }
        if (lane == 0) red[w] = best;
        __syncthreads();
        if (t < 32) {
            unsigned long long b2 = red[t];
#pragma unroll
            for (int off = 16; off; off >>= 1) {
                unsigned long long o = __shfl_xor_sync(0xFFFFFFFFu, b2, off);
                b2 = max(b2, o);
            }
            if (t == 0) {
                int q = (L_SEQ - 1) - (int)(b2 & 0xFFFFFFFFu);
                g_topk[bh * NU + it] = q;
                sk[q] = 0ull;
            }
        }
        __syncthreads();
    }
}

// ---------------- attention partials ----------------
// Block: (bh, 128-key chunk), 256 threads = 8 tu-groups (warps) x 32 tk.
// Phase A: S[48u][128k] = Q_sel @ K^T, thread tile 6u x 4k (24 FMA / LDS.128).
// Phase B: O[48u][64d]  = P @ V,      thread tile 6u x 2d.
__global__ void __launch_bounds__(256) k_attn(const float* __restrict__ Q, const float* __restrict__ K,
                       const float* __restrict__ V, const int* __restrict__ mask) {
    extern __shared__ float smem[];
    float* sQt = smem;                       // [d][u] stride 48
    float* sKT = smem + SQT_FLOATS;          // [d][k] stride 132; reused as P [u][k]
    float* sV  = smem + SQT_FLOATS + SKT_FLOATS; // [k][d] stride 64

    int bh = blockIdx.x >> 5, c = blockIdx.x & 31;
    int b = bh >> 3, h = bh & 7;
    int t = threadIdx.x;
    int tk = t & 31, tu = t >> 5;            // warp == tu group
    int k0 = c * CHUNK;

    // ---- load tiles ----
    for (int i = t; i < 64 * 48; i += 256) {
        int d = i / 48, u = i - d * 48;
        float v = 0.0f;
        if (u < NU) {
            int q = g_topk[bh * NU + u];
            v = Q[((size_t)(b * L_SEQ + q) * NH + h) * DDIM + d];
        }
        sQt[i] = v;
    }
    for (int i = t; i < CHUNK * 64; i += 256) {
        int k = i >> 6, d = i & 63;
        sKT[d * SKT_STRIDE + k] = K[((size_t)(b * L_SEQ + k0 + k) * NH + h) * DDIM + d];
    }
    for (int i = t; i < CHUNK * 64; i += 256) {
        int k = i >> 6, d = i & 63;
        sV[(k << 6) + d] = V[((size_t)(b * L_SEQ + k0 + k) * NH + h) * DDIM + d];
    }
    __syncthreads();

    // ---- phase A: scores, 6u x 4k per thread ----
    float acc[6][4];
#pragma unroll
    for (int i = 0; i < 6; i++)
#pragma unroll
        for (int j = 0; j < 4; j++) acc[i][j] = 0.0f;

#pragma unroll 4
    for (int d = 0; d < 64; d++) {
        float2 q01 = *(float2*)&sQt[d * 48 + 6 * tu];
        float2 q23 = *(float2*)&sQt[d * 48 + 6 * tu + 2];
        float2 q45 = *(float2*)&sQt[d * 48 + 6 * tu + 4];
        float4 kv = *(float4*)&sKT[d * SKT_STRIDE + 4 * tk];
        acc[0][0] += q01.x * kv.x; acc[0][1] += q01.x * kv.y; acc[0][2] += q01.x * kv.z; acc[0][3] += q01.x * kv.w;
        acc[1][0] += q01.y * kv.x; acc[1][1] += q01.y * kv.y; acc[1][2] += q01.y * kv.z; acc[1][3] += q01.y * kv.w;
        acc[2][0] += q23.x * kv.x; acc[2][1] += q23.x * kv.y; acc[2][2] += q23.x * kv.z; acc[2][3] += q23.x * kv.w;
        acc[3][0] += q23.y * kv.x; acc[3][1] += q23.y * kv.y; acc[3][2] += q23.y * kv.z; acc[3][3] += q23.y * kv.w;
        acc[4][0] += q45.x * kv.x; acc[4][1] += q45.x * kv.y; acc[4][2] += q45.x * kv.z; acc[4][3] += q45.x * kv.w;
        acc[5][0] += q45.y * kv.x; acc[5][1] += q45.y * kv.y; acc[5][2] += q45.y * kv.z; acc[5][3] += q45.y * kv.w;
    }

    // mask + scale
    int4 mk = *(const int4*)&mask[b * L_SEQ + k0 + 4 * tk];
#pragma unroll
    for (int i = 0; i < 6; i++) {
        acc[i][0] = mk.x ? acc[i][0] * 0.125f : NEG_BIG;
        acc[i][1] = mk.y ? acc[i][1] * 0.125f : NEG_BIG;
        acc[i][2] = mk.z ? acc[i][2] * 0.125f : NEG_BIG;
        acc[i][3] = mk.w ? acc[i][3] * 0.125f : NEG_BIG;
    }

    // softmax stats per u: full-warp reductions (warp == tu group)
    float m_i[6], l_i[6];
#pragma unroll
    for (int i = 0; i < 6; i++) {
        float m = fmaxf(fmaxf(acc[i][0], acc[i][1]), fmaxf(acc[i][2], acc[i][3]));
#pragma unroll
        for (int off = 16; off; off >>= 1)
            m = fmaxf(m, __shfl_xor_sync(0xFFFFFFFFu, m, off));
        float l = 0.0f;
#pragma unroll
        for (int j = 0; j < 4; j++) {
            float e = (acc[i][j] <= 0.5f * NEG_BIG) ? 0.0f : __expf(acc[i][j] - m);
            acc[i][j] = e;
            l += e;
        }
#pragma unroll
        for (int off = 16; off; off >>= 1)
            l += __shfl_xor_sync(0xFFFFFFFFu, l, off);
        m_i[i] = m; l_i[i] = l;
    }
    __syncthreads();   // all reads of sKT (K^T) done

    // write P into sKT ([u][k]) + m,l
#pragma unroll
    for (int i = 0; i < 6; i++) {
        int u = 6 * tu + i;
        *(float4*)&sKT[u * SKT_STRIDE + 4 * tk] = make_float4(acc[i][0], acc[i][1], acc[i][2], acc[i][3]);
        if (tk == 0 && u < NU) {
            float* part = g_part + ((size_t)blockIdx.x * NU + u) * PART_STRIDE;
            part[0] = m_i[i];
            part[1] = l_i[i];
        }
    }
    __syncthreads();

    // ---- phase B: O_partial = P @ V, 6u x 2d per thread ----
    int td = tk;                              // 0..31 -> float2 over 64 d
    float2 ob[6];
#pragma unroll
    for (int i = 0; i < 6; i++) ob[i] = make_float2(0.0f, 0.0f);

#pragma unroll 4
    for (int kk = 0; kk < CHUNK; kk++) {
        float2 vv = *(float2*)&sV[(kk << 6) + 2 * td];
        float p0 = sKT[(6 * tu + 0) * SKT_STRIDE + kk];
        float p1 = sKT[(6 * tu + 1) * SKT_STRIDE + kk];
        float p2 = sKT[(6 * tu + 2) * SKT_STRIDE + kk];
        float p3 = sKT[(6 * tu + 3) * SKT_STRIDE + kk];
        float p4 = sKT[(6 * tu + 4) * SKT_STRIDE + kk];
        float p5 = sKT[(6 * tu + 5) * SKT_STRIDE + kk];
        ob[0].x += p0 * vv.x; ob[0].y += p0 * vv.y;
        ob[1].x += p1 * vv.x; ob[1].y += p1 * vv.y;
        ob[2].x += p2 * vv.x; ob[2].y += p2 * vv.y;
        ob[3].x += p3 * vv.x; ob[3].y += p3 * vv.y;
        ob[4].x += p4 * vv.x; ob[4].y += p4 * vv.y;
        ob[5].x += p5 * vv.x; ob[5].y += p5 * vv.y;
    }
#pragma unroll
    for (int i = 0; i < 6; i++) {
        int u = 6 * tu + i;
        if (u < NU) {
            float* part = g_part + ((size_t)blockIdx.x * NU + u) * PART_STRIDE;
            *(float2*)&part[4 + 2 * td] = ob[i];
        }
    }
}

// ---------------- combine split-K partials ----------------
__global__ void k_comb(float* __restrict__ out) {
    int bu = blockIdx.x;
    int bh = bu / NU, u = bu % NU;
    int b = bh >> 3, h = bh & 7;
    int d = threadIdx.x;

    float m = NEG_BIG;
#pragma unroll 8
    for (int c = 0; c < NCHUNK; c++)
        m = fmaxf(m, g_part[((size_t)(bh * NCHUNK + c) * NU + u) * PART_STRIDE]);
    float l = 0.0f, acc = 0.0f;
#pragma unroll 8
    for (int c = 0; c < NCHUNK; c++) {
        const float* part = g_part + ((size_t)(bh * NCHUNK + c) * NU + u) * PART_STRIDE;
        float mc = part[0];
        float sc = (mc <= 0.5f * NEG_BIG) ? 0.0f : __expf(mc - m);
        l += part[1] * sc;
        acc += sc * part[4 + d];
    }
    out[((size_t)(b * NU + u) * NH + h) * DDIM + d] = acc / l;
}

// ---------------- launch ----------------
extern "C" void kernel_launch(void* const* d_in, const int* in_sizes, int n_in,
                              void* d_out, int out_size) {
    const float* Q = (const float*)d_in[0];
    const float* K = (const float*)d_in[1];
    const float* V = (const float*)d_in[2];
    const int* mask = (const int*)d_in[3];
    float* out = (float*)d_out;

    cudaFuncSetAttribute(k_attn, cudaFuncAttributeMaxDynamicSharedMemorySize, SMEM_BYTES);

    // lower_key = 2nd child of foldlike split(key(1)) = tf2x32(key=(0,1), ctr=(0,1))
    unsigned s0 = 0u, s1 = 1u;
    tf2x32(0u, 1u, s0, s1);

    k_idx<<<(NIDX + 255) / 256, 256>>>(s0, s1);
    k_M<<<(NBH * L_SEQ) / 8, 256>>>(Q, K);
    k_topk<<<NBH, 1024>>>();
    k_attn<<<NBH * NCHUNK, 256, SMEM_BYTES>>>(Q, K, V, mask);
    k_comb<<<NBH * NU, 64>>>(out);
}